// round 8
// baseline (speedup 1.0000x reference)
#include <cuda_runtime.h>
#include <math.h>

#define BB 4
#define NN 512
#define KLEN 512
#define DD 64
static __device__ __constant__ const float kC2 = 0.36067376022224085f; // 1/(TAU*ln2), TAU=4

// ---------------- scratch (no allocations allowed) ----------------
__device__ float g_hq [BB * NN * DD];    // Q @ Wq
__device__ float g_hkb[BB * KLEN * DD];  // K @ Wk + b1
__device__ float g_M   [BB * NN];        // row max of logits
__device__ float g_invL[BB * NN];        // 1 / sum exp((res-M)/TAU)

// ---------------- kernel 1: projections -----------------
// hq[b,n,e] = sum_d Q[b,n,d] * W1[2d, e]
// hkb[b,k,e] = sum_d K[b,k,d] * W1[2d+1, e] + b1[e]
// block = 256 threads = 4 rows x 64 e-columns; grid = 4096/4 = 1024
__global__ void k_proj(const float* __restrict__ Q, const float* __restrict__ Kin,
                       const float* __restrict__ W1, const float* __restrict__ b1) {
    __shared__ float sW[128 * 64];   // 32 KB
    __shared__ float sIn[4 * 64];
    int tid = threadIdx.x;
    #pragma unroll
    for (int i = 0; i < 32; ++i) sW[i * 256 + tid] = W1[i * 256 + tid];

    int rl = tid >> 6;          // row within block 0..3
    int e  = tid & 63;
    int grow = blockIdx.x * 4 + rl;          // 0..4095
    bool isK = grow >= BB * NN;              // first 2048 rows are Q rows
    int row  = isK ? (grow - BB * NN) : grow;
    const float* src = (isK ? Kin : Q) + row * DD;
    sIn[rl * 64 + e] = src[e];
    __syncthreads();

    float acc = isK ? b1[e] : 0.0f;
    const float* si = sIn + rl * 64;
    int off = isK ? 64 : 0;   // W1[(2d+1),e] for K path
    #pragma unroll
    for (int d = 0; d < 64; ++d)
        acc = fmaf(si[d], sW[d * 128 + off + e], acc);
    (isK ? g_hkb : g_hq)[row * DD + e] = acc;
}

// ---------------- kernel 2: res logits -----------------
// res[b,n,k] = sum_d relu(hq[b,n,d] + hkb[b,k,d]) * W2[d]   (b2 dropped: softmax-invariant)
// grid: (ktile=8, ntile=16, b=4); block 256 = 8 warps.
// warp w handles k = ktile*64 + w*8 .. +7; lane = one of 32 n's -> hkb LDS is broadcast.
__global__ void k_res(const float* __restrict__ W2, float* __restrict__ attp) {
    __shared__ float s_hkb[64 * DD];   // 16 KB tile of hkb rows
    int tid  = threadIdx.x;
    int lane = tid & 31, wid = tid >> 5;
    int b = blockIdx.z, ktile = blockIdx.x, ntile = blockIdx.y;

    const float4* g4 = (const float4*)(g_hkb + (b * KLEN + ktile * 64) * DD);
    float4* s4 = (float4*)s_hkb;
    #pragma unroll
    for (int i = 0; i < 4; ++i) s4[tid + i * 256] = g4[tid + i * 256];
    __syncthreads();

    int n = ntile * 32 + lane;
    const float* hq_row = g_hq + (b * NN + n) * DD;

    float acc[8];
    #pragma unroll
    for (int i = 0; i < 8; ++i) acc[i] = 0.0f;

    #pragma unroll
    for (int dc = 0; dc < 64; dc += 16) {
        float hqr[16], w2r[16];
        #pragma unroll
        for (int j = 0; j < 4; ++j) {
            float4 a = __ldg((const float4*)(hq_row + dc + 4 * j));
            float4 w = __ldg((const float4*)(W2 + dc + 4 * j));
            hqr[4*j+0] = a.x; hqr[4*j+1] = a.y; hqr[4*j+2] = a.z; hqr[4*j+3] = a.w;
            w2r[4*j+0] = w.x; w2r[4*j+1] = w.y; w2r[4*j+2] = w.z; w2r[4*j+3] = w.w;
        }
        #pragma unroll
        for (int kk = 0; kk < 8; ++kk) {
            const float* hk = s_hkb + (wid * 8 + kk) * DD + dc;
            float a = acc[kk];
            #pragma unroll
            for (int j = 0; j < 4; ++j) {
                float4 h = *(const float4*)(hk + 4 * j);   // broadcast across lanes
                a = fmaf(fmaxf(hqr[4*j+0] + h.x, 0.0f), w2r[4*j+0], a);
                a = fmaf(fmaxf(hqr[4*j+1] + h.y, 0.0f), w2r[4*j+1], a);
                a = fmaf(fmaxf(hqr[4*j+2] + h.z, 0.0f), w2r[4*j+2], a);
                a = fmaf(fmaxf(hqr[4*j+3] + h.w, 0.0f), w2r[4*j+3], a);
            }
            acc[kk] = a;
        }
    }

    float* dst = attp + (((long)b * NN + n) * KLEN + ktile * 64 + wid * 8);
    ((float4*)dst)[0] = make_float4(acc[0], acc[1], acc[2], acc[3]);
    ((float4*)dst)[1] = make_float4(acc[4], acc[5], acc[6], acc[7]);
}

// ---------------- kernel 3: per-row softmax stats -----------------
// warp per row; grid 256 x (8 warps) = 2048 rows
__global__ void k_stats(const float* __restrict__ attp) {
    int tid = threadIdx.x, lane = tid & 31, wid = tid >> 5;
    int row = blockIdx.x * 8 + wid;   // 0..2047
    const float4* p = (const float4*)(attp + (long)row * KLEN);
    float v[16];
    #pragma unroll
    for (int j = 0; j < 4; ++j) {
        float4 t = p[j * 32 + lane];
        v[4*j+0] = t.x; v[4*j+1] = t.y; v[4*j+2] = t.z; v[4*j+3] = t.w;
    }
    float m = v[0];
    #pragma unroll
    for (int i = 1; i < 16; ++i) m = fmaxf(m, v[i]);
    #pragma unroll
    for (int s = 16; s; s >>= 1) m = fmaxf(m, __shfl_xor_sync(0xffffffffu, m, s));
    float sum = 0.0f;
    #pragma unroll
    for (int i = 0; i < 16; ++i) sum += exp2f((v[i] - m) * kC2);
    #pragma unroll
    for (int s = 16; s; s >>= 1) sum += __shfl_xor_sync(0xffffffffu, sum, s);
    if (lane == 0) { g_M[row] = m; g_invL[row] = 1.0f / sum; }
}

// ---------------- kernel 4: att + out = att @ V -----------------
// block per (b, 16 n-rows); V_b + att tile in dynamic smem.
#define ATT_STRIDE 516   // 512 + 4 pad: kills the 2048B bank alias between rows
__global__ void k_out(const float* __restrict__ V, float* __restrict__ attp,
                      float* __restrict__ outp) {
    extern __shared__ float sm[];
    float* Vs   = sm;                 // 512*64 = 32768 floats (128 KB)
    float* atts = sm + KLEN * DD;     // 16 * 516 floats
    int tid = threadIdx.x;
    int b = blockIdx.y, nt = blockIdx.x;    // nt 0..31

    // load V_b into smem
    const float4* vg = (const float4*)(V + (long)b * KLEN * DD);
    float4* vs4 = (float4*)Vs;
    #pragma unroll
    for (int i = 0; i < 32; ++i) vs4[tid + i * 256] = vg[tid + i * 256];

    // normalize att for our 16 rows; write to output AND smem
    int rowbase = b * NN + nt * 16;
    #pragma unroll 2
    for (int i = tid; i < 16 * KLEN; i += 256) {
        int r = i >> 9, k = i & 511;
        int row = rowbase + r;
        float lg = attp[(long)row * KLEN + k];
        float a = exp2f((lg - g_M[row]) * kC2) * g_invL[row];
        attp[(long)row * KLEN + k] = a;
        atts[r * ATT_STRIDE + k] = a;
    }
    __syncthreads();

    // GEMV: thread = (row r, 4-wide d-group dg)
    int r = tid >> 4, dg = tid & 15;
    const float4* vrow = (const float4*)Vs;
    const float* ar = atts + r * ATT_STRIDE;
    float4 acc = make_float4(0.f, 0.f, 0.f, 0.f);
    #pragma unroll 8
    for (int k = 0; k < KLEN; ++k) {
        float a = ar[k];
        float4 vv = vrow[k * 16 + dg];
        acc.x = fmaf(a, vv.x, acc.x);
        acc.y = fmaf(a, vv.y, acc.y);
        acc.z = fmaf(a, vv.z, acc.z);
        acc.w = fmaf(a, vv.w, acc.w);
    }
    ((float4*)(outp + (long)(rowbase + r) * DD))[dg] = acc;
}

// ---------------- launch -----------------
extern "C" void kernel_launch(void* const* d_in, const int* in_sizes, int n_in,
                              void* d_out, int out_size) {
    const float* Q   = (const float*)d_in[0];
    const float* Kin = (const float*)d_in[1];
    const float* V   = (const float*)d_in[2];
    const float* W1  = (const float*)d_in[3];
    const float* b1  = (const float*)d_in[4];
    const float* W2  = (const float*)d_in[5];
    // b2 (d_in[6]) intentionally unused: softmax is invariant to a constant shift.

    float* outp = (float*)d_out;                 // out: B*N*D = 131072 floats
    float* attp = outp + BB * NN * DD;           // att: B*N*KLEN = 1048576 floats

    const int smem_k3 = (KLEN * DD + 16 * ATT_STRIDE) * (int)sizeof(float); // 164096 B
    cudaFuncSetAttribute(k_out, cudaFuncAttributeMaxDynamicSharedMemorySize, smem_k3);

    k_proj <<<1024, 256>>>(Q, Kin, W1, b1);
    k_res  <<<dim3(8, 16, 4), 256>>>(W2, attp);
    k_stats<<<256, 256>>>(attp);
    k_out  <<<dim3(32, 4), 256, smem_k3>>>(V, attp, outp);
}

// round 10
// speedup vs baseline: 1.1702x; 1.1702x over previous
#include <cuda_runtime.h>
#include <stdint.h>
#include <math.h>

#define BB 4
#define NN 512
#define KLEN 512
#define DD 64
static __device__ __constant__ const float kC2 = 0.36067376022224085f; // 1/(TAU*ln2), TAU=4

// ---------------- scratch ----------------
__device__ float g_hq [BB * NN * DD];    // Q @ Wq
__device__ float g_hkb[BB * KLEN * DD];  // K @ Wk + b1

// ---------------- kernel 1: projections (unchanged) -----------------
__global__ void k_proj(const float* __restrict__ Q, const float* __restrict__ Kin,
                       const float* __restrict__ W1, const float* __restrict__ b1) {
    __shared__ float sW[128 * 64];
    __shared__ float sIn[4 * 64];
    int tid = threadIdx.x;
    #pragma unroll
    for (int i = 0; i < 32; ++i) sW[i * 256 + tid] = W1[i * 256 + tid];

    int rl = tid >> 6;
    int e  = tid & 63;
    int grow = blockIdx.x * 4 + rl;
    bool isK = grow >= BB * NN;
    int row  = isK ? (grow - BB * NN) : grow;
    const float* src = (isK ? Kin : Q) + row * DD;
    sIn[rl * 64 + e] = src[e];
    __syncthreads();

    float acc = isK ? b1[e] : 0.0f;
    const float* si = sIn + rl * 64;
    int off = isK ? 64 : 0;
    #pragma unroll
    for (int d = 0; d < 64; ++d)
        acc = fmaf(si[d], sW[d * 128 + off + e], acc);
    (isK ? g_hkb : g_hq)[row * DD + e] = acc;
}

// ---------------- kernel 2: res logits (unchanged) -----------------
__global__ void k_res(const float* __restrict__ W2, float* __restrict__ attp) {
    __shared__ float s_hkb[64 * DD];
    int tid  = threadIdx.x;
    int lane = tid & 31, wid = tid >> 5;
    int b = blockIdx.z, ktile = blockIdx.x, ntile = blockIdx.y;

    const float4* g4 = (const float4*)(g_hkb + (b * KLEN + ktile * 64) * DD);
    float4* s4 = (float4*)s_hkb;
    #pragma unroll
    for (int i = 0; i < 4; ++i) s4[tid + i * 256] = g4[tid + i * 256];
    __syncthreads();

    int n = ntile * 32 + lane;
    const float* hq_row = g_hq + (b * NN + n) * DD;

    float acc[8];
    #pragma unroll
    for (int i = 0; i < 8; ++i) acc[i] = 0.0f;

    #pragma unroll
    for (int dc = 0; dc < 64; dc += 16) {
        float hqr[16], w2r[16];
        #pragma unroll
        for (int j = 0; j < 4; ++j) {
            float4 a = __ldg((const float4*)(hq_row + dc + 4 * j));
            float4 w = __ldg((const float4*)(W2 + dc + 4 * j));
            hqr[4*j+0] = a.x; hqr[4*j+1] = a.y; hqr[4*j+2] = a.z; hqr[4*j+3] = a.w;
            w2r[4*j+0] = w.x; w2r[4*j+1] = w.y; w2r[4*j+2] = w.z; w2r[4*j+3] = w.w;
        }
        #pragma unroll
        for (int kk = 0; kk < 8; ++kk) {
            const float* hk = s_hkb + (wid * 8 + kk) * DD + dc;
            float a = acc[kk];
            #pragma unroll
            for (int j = 0; j < 4; ++j) {
                float4 h = *(const float4*)(hk + 4 * j);
                a = fmaf(fmaxf(hqr[4*j+0] + h.x, 0.0f), w2r[4*j+0], a);
                a = fmaf(fmaxf(hqr[4*j+1] + h.y, 0.0f), w2r[4*j+1], a);
                a = fmaf(fmaxf(hqr[4*j+2] + h.z, 0.0f), w2r[4*j+2], a);
                a = fmaf(fmaxf(hqr[4*j+3] + h.w, 0.0f), w2r[4*j+3], a);
            }
            acc[kk] = a;
        }
    }

    float* dst = attp + (((long)b * NN + n) * KLEN + ktile * 64 + wid * 8);
    ((float4*)dst)[0] = make_float4(acc[0], acc[1], acc[2], acc[3]);
    ((float4*)dst)[1] = make_float4(acc[4], acc[5], acc[6], acc[7]);
}

// ---------------- kernel 3: softmax (stats + normalize fused) -----------------
// warp per row; row held entirely in registers, so normalize in-place here.
__global__ void k_stats(float* __restrict__ attp) {
    int tid = threadIdx.x, lane = tid & 31, wid = tid >> 5;
    int row = blockIdx.x * 8 + wid;   // 0..2047
    float4* p = (float4*)(attp + (long)row * KLEN);
    float v[16];
    #pragma unroll
    for (int j = 0; j < 4; ++j) {
        float4 t = p[j * 32 + lane];
        v[4*j+0] = t.x; v[4*j+1] = t.y; v[4*j+2] = t.z; v[4*j+3] = t.w;
    }
    float m = v[0];
    #pragma unroll
    for (int i = 1; i < 16; ++i) m = fmaxf(m, v[i]);
    #pragma unroll
    for (int s = 16; s; s >>= 1) m = fmaxf(m, __shfl_xor_sync(0xffffffffu, m, s));
    float e[16];
    float sum = 0.0f;
    #pragma unroll
    for (int i = 0; i < 16; ++i) { e[i] = exp2f((v[i] - m) * kC2); sum += e[i]; }
    #pragma unroll
    for (int s = 16; s; s >>= 1) sum += __shfl_xor_sync(0xffffffffu, sum, s);
    float inv = 1.0f / sum;   // all lanes have it (butterfly reduction)
    #pragma unroll
    for (int j = 0; j < 4; ++j)
        p[j * 32 + lane] = make_float4(e[4*j+0] * inv, e[4*j+1] * inv,
                                       e[4*j+2] * inv, e[4*j+3] * inv);
}

// ---------------- kernel 4: out = att @ V (register-tiled, cp.async double-buffered) ---
// block = 16 rows x 64 cols, 256 threads, thread = 2 rows x 2 cols.
// K tiled by 128: V tile 128x64 (32KB), att tile 16x(128, stride 132) (~8.25KB), x2 buffers.
#define KT 128
#define AST 132                            // att tile row stride (16B-aligned: 528B)
#define VT_F (KT * DD)                     // 8192 floats
#define AT_F (16 * AST)                    // 2112 floats
#define SMEM_OUT ((2 * (VT_F + AT_F)) * 4) // 82432 bytes

__device__ __forceinline__ void cp16(uint32_t dst, const void* src) {
    asm volatile("cp.async.cg.shared.global [%0], [%1], 16;\n" :: "r"(dst), "l"(src));
}

__global__ void __launch_bounds__(256, 1)
k_out(const float* __restrict__ V, const float* __restrict__ attp,
      float* __restrict__ outp) {
    extern __shared__ float sm[];
    float* Vs[2] = { sm,             sm + VT_F };
    float* As[2] = { sm + 2 * VT_F,  sm + 2 * VT_F + AT_F };

    int tid = threadIdx.x;
    int b = blockIdx.y, nt = blockIdx.x;        // nt 0..31
    int rowbase = b * NN + nt * 16;

    const float* Vb = V + (long)b * KLEN * DD;
    const float* Ab = attp + (long)rowbase * KLEN;

    uint32_t sV0 = (uint32_t)__cvta_generic_to_shared(Vs[0]);
    uint32_t sV1 = (uint32_t)__cvta_generic_to_shared(Vs[1]);
    uint32_t sA0 = (uint32_t)__cvta_generic_to_shared(As[0]);
    uint32_t sA1 = (uint32_t)__cvta_generic_to_shared(As[1]);
    uint32_t sV[2] = { sV0, sV1 }, sA[2] = { sA0, sA1 };

    // att tile mapping: thread -> (row ar, 8 k's starting at ak)
    int ar = tid >> 4;                 // 0..15
    int ak = (tid & 15) * 8;           // 0..120

    // issue loads for tile t into buffer bu
    auto issue = [&](int t, int bu) {
        int k0 = t * KT;
        const float* vsrc = Vb + k0 * DD;            // contiguous 32KB
        #pragma unroll
        for (int j = 0; j < 8; ++j)
            cp16(sV[bu] + (tid + j * 256) * 16, vsrc + (tid + j * 256) * 4);
        const float* asrc = Ab + (long)ar * KLEN + k0 + ak;
        cp16(sA[bu] + (ar * AST + ak) * 4,     asrc);
        cp16(sA[bu] + (ar * AST + ak + 4) * 4, asrc + 4);
        asm volatile("cp.async.commit_group;\n");
    };

    issue(0, 0);

    int rg = tid & 7, cg = tid >> 3;   // rows 2rg,2rg+1; cols 2cg,2cg+1
    float acc00 = 0.f, acc01 = 0.f, acc10 = 0.f, acc11 = 0.f;

    #pragma unroll
    for (int t = 0; t < KLEN / KT; ++t) {
        int bu = t & 1;
        if (t + 1 < KLEN / KT) {
            issue(t + 1, bu ^ 1);
            asm volatile("cp.async.wait_group 1;\n");
        } else {
            asm volatile("cp.async.wait_group 0;\n");
        }
        __syncthreads();

        const float* A0 = As[bu] + (2 * rg) * AST;
        const float* A1 = A0 + AST;
        const float* Vp = Vs[bu] + 2 * cg;
        #pragma unroll 8
        for (int k = 0; k < KT; ++k) {
            float a0 = A0[k];
            float a1 = A1[k];
            float2 v = *(const float2*)(Vp + k * DD);
            acc00 = fmaf(a0, v.x, acc00);
            acc01 = fmaf(a0, v.y, acc01);
            acc10 = fmaf(a1, v.x, acc10);
            acc11 = fmaf(a1, v.y, acc11);
        }
        __syncthreads();
    }

    int row0 = rowbase + 2 * rg;
    float2* o0 = (float2*)(outp + (long)row0 * DD + 2 * cg);
    float2* o1 = (float2*)(outp + (long)(row0 + 1) * DD + 2 * cg);
    *o0 = make_float2(acc00, acc01);
    *o1 = make_float2(acc10, acc11);
}

// ---------------- launch -----------------
extern "C" void kernel_launch(void* const* d_in, const int* in_sizes, int n_in,
                              void* d_out, int out_size) {
    const float* Q   = (const float*)d_in[0];
    const float* Kin = (const float*)d_in[1];
    const float* V   = (const float*)d_in[2];
    const float* W1  = (const float*)d_in[3];
    const float* b1  = (const float*)d_in[4];
    const float* W2  = (const float*)d_in[5];
    // b2 unused: softmax shift-invariant

    float* outp = (float*)d_out;                 // out: B*N*D
    float* attp = outp + BB * NN * DD;           // att: B*N*KLEN

    cudaFuncSetAttribute(k_out, cudaFuncAttributeMaxDynamicSharedMemorySize, SMEM_OUT);

    k_proj <<<1024, 256>>>(Q, Kin, W1, b1);
    k_res  <<<dim3(8, 16, 4), 256>>>(W2, attp);
    k_stats<<<256, 256>>>(attp);
    k_out  <<<dim3(32, 4), 256, SMEM_OUT>>>(V, attp, outp);
}